// round 10
// baseline (speedup 1.0000x reference)
#include <cuda_runtime.h>
#include <cstdint>

// Problem constants.
#define KB 4
#define KS 4096
#define KH 16
#define KD 64
#define KC 128                 // chunk size (math is chunk-invariant)
#define KN (KS / KC)           // 32 chunks per (b,h)
#define KBH (KB * KH)          // 64
#define KCHUNKS (KBH * KN)     // 2048
#define KROW (KH * KD)         // 1024 floats between consecutive s

// Smem pitches
#define PQ 68     // [row][d]: frag reads at banks 4*grp+tg (conflict-free)
#define PV 72     // [k][n]:  frag reads at banks 8*tg+grp (conflict-free)
#define PS 132    // S [i][j]
#define PKT 133   // K^T in kv kernel: odd pitch -> conflict-free d=lane stores

// Scratch: per-chunk KV outer products -> exclusive prefix states. 32 MiB.
__device__ float g_kv[(size_t)KCHUNKS * KD * KD];

__device__ __forceinline__ unsigned f2tf(float x) {
    unsigned u;
    asm("cvt.rna.tf32.f32 %0, %1;" : "=r"(u) : "f"(x));
    return u;
}

__device__ __forceinline__ void mma_tf32(float* c, const unsigned* a, const unsigned* b) {
    asm volatile(
        "mma.sync.aligned.m16n8k8.row.col.f32.tf32.tf32.f32 "
        "{%0,%1,%2,%3}, {%4,%5,%6,%7}, {%8,%9}, {%0,%1,%2,%3};"
        : "+f"(c[0]), "+f"(c[1]), "+f"(c[2]), "+f"(c[3])
        : "r"(a[0]), "r"(a[1]), "r"(a[2]), "r"(a[3]), "r"(b[0]), "r"(b[1]));
}

// ---------------------------------------------------------------------------
// Kernel A: KV[d][e] = sum_j K[j][d]*V[j][e] per chunk. 64x64x128 per block.
// Block 256 (8 warps, 2x4 grid of 32x16 warp tiles).
// K loaded scalar (d = lane) so transposed STS is conflict-free with PKT odd.
// ---------------------------------------------------------------------------
__global__ __launch_bounds__(256) void kv_kernel(const float* __restrict__ K,
                                                 const float* __restrict__ V) {
    extern __shared__ unsigned sm_u[];
    unsigned* Kt = sm_u;                  // [KD][PKT]  Kt[d][j]
    unsigned* Vs = sm_u + KD * PKT;       // [KC][PV]   Vs[j][e]

    const int g = blockIdx.x;
    const int b = g >> 9;
    const int h = (g >> 5) & (KH - 1);
    const int n = g & (KN - 1);
    const int tid = threadIdx.x;
    const int base = ((b * KS + n * KC) * KH + h) * KD;

    // K: scalar coalesced loads (lane = consecutive d), conflict-free STS.
#pragma unroll
    for (int t = tid; t < KC * KD; t += 256) {
        const int j = t >> 6;
        const int d = t & 63;
        Kt[d * PKT + j] = f2tf(K[base + j * KROW + d]);
    }
    // V: float4 loads, row-major stores.
#pragma unroll
    for (int t = tid; t < KC * KD / 4; t += 256) {
        const int row = t >> 4;
        const int col = (t & 15) << 2;
        const float4 vq = *(const float4*)&V[base + row * KROW + col];
        *(uint4*)&Vs[row * PV + col] =
            make_uint4(f2tf(vq.x), f2tf(vq.y), f2tf(vq.z), f2tf(vq.w));
    }
    __syncthreads();

    const int wid = tid >> 5;
    const int lane = tid & 31;
    const int grp = lane >> 2;
    const int tg = lane & 3;
    const int wm = (wid >> 2) << 5;       // d-origin: 0 or 32
    const int wn = (wid & 3) << 4;        // e-origin: 0,16,32,48

    float acc[2][2][4];
#pragma unroll
    for (int mi = 0; mi < 2; ++mi)
#pragma unroll
        for (int ni = 0; ni < 2; ++ni)
#pragma unroll
            for (int r = 0; r < 4; ++r) acc[mi][ni][r] = 0.0f;

#pragma unroll
    for (int j0 = 0; j0 < KC; j0 += 8) {
        unsigned a[2][4], bb[2][2];
#pragma unroll
        for (int mi = 0; mi < 2; ++mi) {
            const int d = wm + (mi << 4);
            a[mi][0] = Kt[(d + grp) * PKT + j0 + tg];
            a[mi][1] = Kt[(d + grp + 8) * PKT + j0 + tg];
            a[mi][2] = Kt[(d + grp) * PKT + j0 + tg + 4];
            a[mi][3] = Kt[(d + grp + 8) * PKT + j0 + tg + 4];
        }
#pragma unroll
        for (int ni = 0; ni < 2; ++ni) {
            const int e = wn + (ni << 3) + grp;
            bb[ni][0] = Vs[(j0 + tg) * PV + e];
            bb[ni][1] = Vs[(j0 + tg + 4) * PV + e];
        }
#pragma unroll
        for (int mi = 0; mi < 2; ++mi)
#pragma unroll
            for (int ni = 0; ni < 2; ++ni) mma_tf32(acc[mi][ni], a[mi], bb[ni]);
    }

    float* outp = g_kv + (size_t)g * (KD * KD);
#pragma unroll
    for (int mi = 0; mi < 2; ++mi)
#pragma unroll
        for (int ni = 0; ni < 2; ++ni) {
            const int d = wm + (mi << 4) + grp;
            const int e = wn + (ni << 3) + (tg << 1);
            *(float2*)&outp[d * KD + e] = make_float2(acc[mi][ni][0], acc[mi][ni][1]);
            *(float2*)&outp[(d + 8) * KD + e] = make_float2(acc[mi][ni][2], acc[mi][ni][3]);
        }
}

// ---------------------------------------------------------------------------
// Kernel B: in-place exclusive prefix over chunks, float4 per thread.
// Grid 256 = 64 bh * 4; 256 threads; each thread scans 4 consecutive floats.
// ---------------------------------------------------------------------------
__global__ __launch_bounds__(256) void scan_kernel() {
    const int bh = blockIdx.x >> 2;
    const int idx4 = (((blockIdx.x & 3) << 8) + threadIdx.x) << 2;  // 0..4092
    size_t addr = (size_t)bh * KN * (KD * KD) + idx4;

    float4 run = make_float4(0.f, 0.f, 0.f, 0.f);
#pragma unroll 8
    for (int n = 0; n < KN; ++n) {
        float4* p = (float4*)&g_kv[addr];
        const float4 val = *p;
        *p = run;
        run.x += val.x; run.y += val.y; run.z += val.z; run.w += val.w;
        addr += KD * KD;
    }
}

// ---------------------------------------------------------------------------
// Kernel C: O = tril(Q K^T) V + Q * KV_prev, per 128-chunk.
// Block 256 (8 warps). Stage1 warp tile 32x64 (4x2), fully-masked tiles skip
// their MMAs. Stage2 warp tile 32x32; the S.V k-loop truncates at j0<wm+32.
// ---------------------------------------------------------------------------
__global__ __launch_bounds__(256) void out_kernel(const float* __restrict__ Q,
                                                  const float* __restrict__ K,
                                                  const float* __restrict__ V,
                                                  float* __restrict__ O) {
    extern __shared__ unsigned sm_u[];
    unsigned* Qs = sm_u;                          // [KC][PQ]
    unsigned* Ks = Qs + KC * PQ;                  // [KC][PQ]
    unsigned* Vs = Ks + KC * PQ;                  // [KC][PV]
    unsigned* Ps = Vs + KC * PV;                  // [KD][PV]
    unsigned* Ss = Ps + KD * PV;                  // [KC][PS]

    const int g = blockIdx.x;
    const int b = g >> 9;
    const int h = (g >> 5) & (KH - 1);
    const int n = g & (KN - 1);
    const int tid = threadIdx.x;
    const int base = ((b * KS + n * KC) * KH + h) * KD;
    const float* kvp = g_kv + (size_t)g * (KD * KD);

#pragma unroll
    for (int t = tid; t < KC * KD / 4; t += 256) {
        const int row = t >> 4;
        const int col = (t & 15) << 2;
        const int ga = base + row * KROW + col;
        const float4 qq = *(const float4*)&Q[ga];
        *(uint4*)&Qs[row * PQ + col] =
            make_uint4(f2tf(qq.x), f2tf(qq.y), f2tf(qq.z), f2tf(qq.w));
        const float4 kk = *(const float4*)&K[ga];
        *(uint4*)&Ks[row * PQ + col] =
            make_uint4(f2tf(kk.x), f2tf(kk.y), f2tf(kk.z), f2tf(kk.w));
        const float4 vv = *(const float4*)&V[ga];
        *(uint4*)&Vs[row * PV + col] =
            make_uint4(f2tf(vv.x), f2tf(vv.y), f2tf(vv.z), f2tf(vv.w));
    }
#pragma unroll
    for (int t = tid; t < KD * KD / 4; t += 256) {
        const int d = t >> 4;
        const int e = (t & 15) << 2;
        const float4 pp = *(const float4*)&kvp[d * KD + e];
        *(uint4*)&Ps[d * PV + e] =
            make_uint4(f2tf(pp.x), f2tf(pp.y), f2tf(pp.z), f2tf(pp.w));
    }
    __syncthreads();

    const int wid = tid >> 5;
    const int lane = tid & 31;
    const int grp = lane >> 2;
    const int tg = lane & 3;

    // ---- Stage 1: S = Q K^T (128x128x64), warp tile 32x64 (warps 4x2) ----
    {
        const int wm = (wid >> 1) << 5;    // i-origin
        const int wn = (wid & 1) << 6;     // j-origin

        float acc[2][8][4];
#pragma unroll
        for (int mi = 0; mi < 2; ++mi)
#pragma unroll
            for (int ni = 0; ni < 8; ++ni)
#pragma unroll
                for (int r = 0; r < 4; ++r) acc[mi][ni][r] = 0.0f;

        // Fully-masked tile (all j > all i): keep acc at zero, skip MMAs.
        if (wn <= wm + 31) {
#pragma unroll
            for (int d0 = 0; d0 < KD; d0 += 8) {
                unsigned a[2][4], bb[8][2];
#pragma unroll
                for (int mi = 0; mi < 2; ++mi) {
                    const int i = wm + (mi << 4);
                    a[mi][0] = Qs[(i + grp) * PQ + d0 + tg];
                    a[mi][1] = Qs[(i + grp + 8) * PQ + d0 + tg];
                    a[mi][2] = Qs[(i + grp) * PQ + d0 + tg + 4];
                    a[mi][3] = Qs[(i + grp + 8) * PQ + d0 + tg + 4];
                }
#pragma unroll
                for (int ni = 0; ni < 8; ++ni) {
                    const int j = wn + (ni << 3) + grp;
                    bb[ni][0] = Ks[j * PQ + d0 + tg];
                    bb[ni][1] = Ks[j * PQ + d0 + tg + 4];
                }
#pragma unroll
                for (int mi = 0; mi < 2; ++mi)
#pragma unroll
                    for (int ni = 0; ni < 8; ++ni) mma_tf32(acc[mi][ni], a[mi], bb[ni]);
            }
        }

        // Mask (j<=i), store tf32 to Ss[i][j] (zeros for skipped tiles).
#pragma unroll
        for (int mi = 0; mi < 2; ++mi)
#pragma unroll
            for (int ni = 0; ni < 8; ++ni) {
                const int i0r = wm + (mi << 4) + grp;
                const int jc = wn + (ni << 3) + (tg << 1);
                Ss[i0r * PS + jc]     = (jc     <= i0r) ? f2tf(acc[mi][ni][0]) : 0u;
                Ss[i0r * PS + jc + 1] = (jc + 1 <= i0r) ? f2tf(acc[mi][ni][1]) : 0u;
                Ss[(i0r + 8) * PS + jc]     = (jc     <= i0r + 8) ? f2tf(acc[mi][ni][2]) : 0u;
                Ss[(i0r + 8) * PS + jc + 1] = (jc + 1 <= i0r + 8) ? f2tf(acc[mi][ni][3]) : 0u;
            }
    }
    __syncthreads();

    // ---- Stage 2: O = Ss*V + Q*P, warp tile 32x32 (warps 4x2) ----
    {
        const int wm = (wid >> 1) << 5;    // i-origin
        const int wn = (wid & 1) << 5;     // e-origin

        float acc[2][4][4];
#pragma unroll
        for (int mi = 0; mi < 2; ++mi)
#pragma unroll
            for (int ni = 0; ni < 4; ++ni)
#pragma unroll
                for (int r = 0; r < 4; ++r) acc[mi][ni][r] = 0.0f;

        // 2a: sum over j; S[i][j] == 0 for j > i <= wm+31, so stop at wm+32.
        const int jmax = wm + 32;
#pragma unroll 4
        for (int j0 = 0; j0 < jmax; j0 += 8) {
            unsigned a[2][4], bb[4][2];
#pragma unroll
            for (int mi = 0; mi < 2; ++mi) {
                const int i = wm + (mi << 4);
                a[mi][0] = Ss[(i + grp) * PS + j0 + tg];
                a[mi][1] = Ss[(i + grp + 8) * PS + j0 + tg];
                a[mi][2] = Ss[(i + grp) * PS + j0 + tg + 4];
                a[mi][3] = Ss[(i + grp + 8) * PS + j0 + tg + 4];
            }
#pragma unroll
            for (int ni = 0; ni < 4; ++ni) {
                const int e = wn + (ni << 3) + grp;
                bb[ni][0] = Vs[(j0 + tg) * PV + e];
                bb[ni][1] = Vs[(j0 + tg + 4) * PV + e];
            }
#pragma unroll
            for (int mi = 0; mi < 2; ++mi)
#pragma unroll
                for (int ni = 0; ni < 4; ++ni) mma_tf32(acc[mi][ni], a[mi], bb[ni]);
        }

        // 2b: sum over d (64), P = KV_prev
#pragma unroll
        for (int d0 = 0; d0 < KD; d0 += 8) {
            unsigned a[2][4], bb[4][2];
#pragma unroll
            for (int mi = 0; mi < 2; ++mi) {
                const int i = wm + (mi << 4);
                a[mi][0] = Qs[(i + grp) * PQ + d0 + tg];
                a[mi][1] = Qs[(i + grp + 8) * PQ + d0 + tg];
                a[mi][2] = Qs[(i + grp) * PQ + d0 + tg + 4];
                a[mi][3] = Qs[(i + grp + 8) * PQ + d0 + tg + 4];
            }
#pragma unroll
            for (int ni = 0; ni < 4; ++ni) {
                const int e = wn + (ni << 3) + grp;
                bb[ni][0] = Ps[(d0 + tg) * PV + e];
                bb[ni][1] = Ps[(d0 + tg + 4) * PV + e];
            }
#pragma unroll
            for (int mi = 0; mi < 2; ++mi)
#pragma unroll
                for (int ni = 0; ni < 4; ++ni) mma_tf32(acc[mi][ni], a[mi], bb[ni]);
        }

        // Store O.
#pragma unroll
        for (int mi = 0; mi < 2; ++mi)
#pragma unroll
            for (int ni = 0; ni < 4; ++ni) {
                const int i = wm + (mi << 4) + grp;
                const int e = wn + (ni << 3) + (tg << 1);
                *(float2*)&O[base + i * KROW + e] =
                    make_float2(acc[mi][ni][0], acc[mi][ni][1]);
                *(float2*)&O[base + (i + 8) * KROW + e] =
                    make_float2(acc[mi][ni][2], acc[mi][ni][3]);
            }
    }
}

// ---------------------------------------------------------------------------
// Launch
// ---------------------------------------------------------------------------
static const int kKvSmem = (KD * PKT + KC * PV) * (int)sizeof(unsigned);      // 70912
static const int kOutSmem =
    (2 * KC * PQ + KC * PV + KD * PV + KC * PS) * (int)sizeof(unsigned);      // 192512

extern "C" void kernel_launch(void* const* d_in, const int* in_sizes, int n_in,
                              void* d_out, int out_size) {
    const float* q = (const float*)d_in[0];
    const float* k = (const float*)d_in[1];
    const float* v = (const float*)d_in[2];
    float* out = (float*)d_out;

    cudaFuncSetAttribute(kv_kernel, cudaFuncAttributeMaxDynamicSharedMemorySize,
                         kKvSmem);
    cudaFuncSetAttribute(out_kernel, cudaFuncAttributeMaxDynamicSharedMemorySize,
                         kOutSmem);

    kv_kernel<<<KCHUNKS, 256, kKvSmem>>>(k, v);
    scan_kernel<<<KBH * 4, 256>>>();
    out_kernel<<<KCHUNKS, 256, kOutSmem>>>(q, k, v, out);
}